// round 15
// baseline (speedup 1.0000x reference)
#include <cuda_runtime.h>
#include <cuda_bf16.h>

// Dead-code-eliminated Net2 BSDE recurrence.
// ARITHMETIC IS BIT-FROZEN to the passing trajectory (rel_err 1.627573e-05).
// Serial loop: verbatim Round-5 champion (branchless 3-arm select + bit-exact
// two-FMA div3), ~44 cyc/iter frozen floor. Per-step dot: frozen lane mapping
// (lane, +32, +64, +96), frozen 5-level shuffle tree, term3 = s * sqrtf(dt).
//
// Round-15 change (bit-neutral, scheduling only): SPLIT-BARRIER OVERLAP.
//  Group A (warps 0-7): steps 0-7, self-sufficient (per-lane gu computed from
//    the identical expression -> identical bits; own sqrt off-chain). After
//    bar.sync(1,256), thread 0 runs iterations 0-7 while group B finishes.
//  Group B (warps 8-31): steps 8-39 (warps 8-15 dual, k1 = warp+24); gu_s by
//    warps 8-11, bar.sync(3,768) internal; bar.arrive(2,800) on completion.
//  Warp 0 bar.sync(2,800) before iterations 8-39 (expected zero wait).
// No __syncthreads anywhere. Which warp computes a step cannot change bits.

#define D_DIM    100
#define N_STEPS  40
#define NTHREADS 1024

#define BAR_SYNC(b, n)   asm volatile("bar.sync %0, %1;"   :: "r"(b), "r"(n) : "memory")
#define BAR_ARRIVE(b, n) asm volatile("bar.arrive %0, %1;" :: "r"(b), "r"(n) : "memory")

__device__ __forceinline__ float div3(float x) {
    // Correctly-rounded x/3 (== FDIV bits): Brisebarre-Muller two-FMA scheme.
    const float C_HI = 0.33333334f;       // RN(1/3)
    const float C_LO = -9.9341075e-09f;   // RN(1/3 - C_HI) = -1/(3*2^25)
    return __fmaf_rn(x, C_HI, x * C_LO);
}

__global__ void net2_u_kernel(const float* __restrict__ x0,
                              const float* __restrict__ tlist,
                              const float* __restrict__ noise,   // (N_STEPS, D, 1)
                              const float* __restrict__ u0,
                              const float* __restrict__ gu0,     // (D, 1)
                              float* __restrict__ out) {
    __shared__ float term3[N_STEPS];
    __shared__ float s_dt[N_STEPS];
    __shared__ float gu_s[D_DIM];

    const int tid  = threadIdx.x;
    const int warp = tid >> 5;
    const int lane = tid & 31;
    const bool tail = (lane < (D_DIM - 96));   // lane < 4

    if (warp < 8) {
        // ---------------- Group A: steps 0-7, self-sufficient ----------------
        const int k = warp;

        // Stage s_dt (all 40, by warps 0-1: inside barrier-1 group).
        if (warp == 0) s_dt[lane] = tlist[lane];
        if (warp == 1 && lane < 8) s_dt[32 + lane] = tlist[32 + lane];

        float ustart = 0.0f;
        if (tid == 0) ustart = u0[0];

        // Off-chain sqrt for this step (same instruction/bits as before).
        float sq = 0.0f;
        if (lane == 0) sq = sqrtf(tlist[k]);

        // Frozen noise preload.
        const float* nk = noise + k * D_DIM;
        float a0 = nk[lane], a1 = nk[lane + 32], a2 = nk[lane + 64];
        float a3 = 0.0f;
        if (tail) a3 = nk[lane + 96];

        // Per-lane gu, identical expression -> identical bits to gu_s values.
        float g0 = 0.2f * x0[lane]      * gu0[lane];
        float g1 = 0.2f * x0[lane + 32] * gu0[lane + 32];
        float g2 = 0.2f * x0[lane + 64] * gu0[lane + 64];
        float g3 = 0.0f;
        if (tail) g3 = 0.2f * x0[lane + 96] * gu0[lane + 96];

        // Frozen accumulate + tree.
        float s = 0.0f;
        s += g0 * a0;
        s += g1 * a1;
        s += g2 * a2;
        if (tail) s += g3 * a3;
        #pragma unroll
        for (int off = 16; off > 0; off >>= 1)
            s += __shfl_down_sync(0xFFFFFFFFu, s, off);
        if (lane == 0)
            term3[k] = s * sq;

        BAR_SYNC(1, 256);                 // term3[0..7], s_dt, gu done in-group

        if (warp == 0) {
            float u = 0.0f;
            if (lane == 0) {
                u = ustart;
                #pragma unroll
                for (int k2 = 0; k2 < 8; k2++) {
                    float dt = s_dt[k2];
                    float low  = div3(-0.02f * u) - 0.02f * u;
                    float high = div3(-0.002f * u) - 0.02f * u;
                    float mid  = div3(-(70.0f - 50.0f) / (0.02f - 0.2f) * (u - 50.0f)) * u
                                 - (0.2f / 3.0f) * u - 0.02f * u;
                    float f = (u < 50.0f) ? low : ((u >= 70.0f) ? high : mid);
                    u = u - f * dt + term3[k2];
                }
            }

            BAR_SYNC(2, 800);             // wait for group B's term3[8..39]

            if (lane == 0) {
                #pragma unroll
                for (int k2 = 8; k2 < N_STEPS; k2++) {
                    float dt = s_dt[k2];
                    float low  = div3(-0.02f * u) - 0.02f * u;
                    float high = div3(-0.002f * u) - 0.02f * u;
                    float mid  = div3(-(70.0f - 50.0f) / (0.02f - 0.2f) * (u - 50.0f)) * u
                                 - (0.2f / 3.0f) * u - 0.02f * u;
                    float f = (u < 50.0f) ? low : ((u >= 70.0f) ? high : mid);
                    u = u - f * dt + term3[k2];
                }
                out[0] = u;
            }
        }
        // warps 1-7 exit here.
    } else {
        // ---------------- Group B: steps 8-39 ----------------
        // warps 8-15: k0 = warp (8..15), k1 = warp + 24 (32..39)
        // warps 16-31: k0 = warp (16..31)
        int k0 = warp;
        int k1 = (warp < 16) ? (warp + 24) : -1;

        // Off-chain sqrts (lane 0).
        float sq0 = 0.0f, sq1 = 0.0f;
        if (lane == 0) {
            sq0 = sqrtf(tlist[k0]);
            if (k1 >= 0) sq1 = sqrtf(tlist[k1]);
        }

        // Frozen noise preload.
        float a0, a1, a2, a3 = 0.0f;
        float b0 = 0.0f, b1 = 0.0f, b2 = 0.0f, b3 = 0.0f;
        {
            const float* n0 = noise + k0 * D_DIM;
            a0 = n0[lane]; a1 = n0[lane + 32]; a2 = n0[lane + 64];
            if (tail) a3 = n0[lane + 96];
            if (k1 >= 0) {
                const float* n1 = noise + k1 * D_DIM;
                b0 = n1[lane]; b1 = n1[lane + 32]; b2 = n1[lane + 64];
                if (tail) b3 = n1[lane + 96];
            }
        }

        // gu_s produced once by warps 8-11 (threads 256-355).
        if (tid >= 256 && tid < 256 + D_DIM) {
            int i = tid - 256;
            gu_s[i] = 0.2f * x0[i] * gu0[i];
        }

        BAR_SYNC(3, 768);                 // gu_s ready within group B

        float g0 = gu_s[lane], g1 = gu_s[lane + 32], g2 = gu_s[lane + 64];
        float g3 = tail ? gu_s[lane + 96] : 0.0f;

        if (k1 >= 0) {
            float s0 = 0.0f, s1 = 0.0f;
            s0 += g0 * a0;  s1 += g0 * b0;
            s0 += g1 * a1;  s1 += g1 * b1;
            s0 += g2 * a2;  s1 += g2 * b2;
            if (tail) { s0 += g3 * a3; s1 += g3 * b3; }
            #pragma unroll
            for (int off = 16; off > 0; off >>= 1) {
                s0 += __shfl_down_sync(0xFFFFFFFFu, s0, off);
                s1 += __shfl_down_sync(0xFFFFFFFFu, s1, off);
            }
            if (lane == 0) {
                term3[k0] = s0 * sq0;
                term3[k1] = s1 * sq1;
            }
        } else {
            float s = 0.0f;
            s += g0 * a0;
            s += g1 * a1;
            s += g2 * a2;
            if (tail) s += g3 * a3;
            #pragma unroll
            for (int off = 16; off > 0; off >>= 1)
                s += __shfl_down_sync(0xFFFFFFFFu, s, off);
            if (lane == 0)
                term3[k0] = s * sq0;
        }

        BAR_ARRIVE(2, 800);               // commit term3[8..39] to warp 0
    }
}

extern "C" void kernel_launch(void* const* d_in, const int* in_sizes, int n_in,
                              void* d_out, int out_size) {
    const float* x0    = (const float*)d_in[0];
    const float* tlist = (const float*)d_in[1];
    const float* noise = (const float*)d_in[2];
    const float* u0    = (const float*)d_in[3];
    const float* gu0   = (const float*)d_in[4];
    float* out = (float*)d_out;

    net2_u_kernel<<<1, NTHREADS>>>(x0, tlist, noise, u0, gu0, out);
}